// round 6
// baseline (speedup 1.0000x reference)
#include <cuda_runtime.h>
#include <cuda_bf16.h>

#define W_IN 160
#define H_IN 160
#define HW   (H_IN * W_IN)
#define C_IN 256
#define POOLED 7
#define MAXT 5                     // max footprint side (3*sw <= 2.16 => <=5)
#define MAXSTRIDE 25               // max per-channel smem stride
#define NWARP 8

__device__ __forceinline__ void cp_async4(float* smem_dst, const float* gmem_src) {
    unsigned s = (unsigned)__cvta_generic_to_shared(smem_dst);
    asm volatile("cp.async.ca.shared.global [%0], [%1], 4;\n" :: "r"(s), "l"(gmem_src));
}

__global__ __launch_bounds__(C_IN, 6)
void dcnv2_pool_kernel(const float* __restrict__ inp,
                       const float* __restrict__ rois,
                       const float* __restrict__ offset,
                       float* __restrict__ out,
                       int N)
{
    __shared__ float tile[C_IN * MAXSTRIDE];     // 25.6 KB
    __shared__ float wacc[NWARP][32];            // per-warp accumulated weights (25 used)

    const int bin = blockIdx.x;
    const int n   = blockIdx.y;
    const int ph  = bin / POOLED;
    const int pw  = bin % POOLED;
    const int tid = threadIdx.x;
    const int lane = tid & 31;
    const int warp = tid >> 5;

    // ---- ROI geometry (uniform across block; every thread computes) ----
    const float* roi = rois + n * 5;
    const int   b  = (int)__ldg(&roi[0]);
    const float rsw = rintf(__ldg(&roi[1])) * 0.0625f - 0.5f;
    const float rsh = rintf(__ldg(&roi[2])) * 0.0625f - 0.5f;
    const float rew = (rintf(__ldg(&roi[3])) + 1.0f) * 0.0625f - 0.5f;
    const float reh = (rintf(__ldg(&roi[4])) + 1.0f) * 0.0625f - 0.5f;
    const float rw  = fmaxf(rew - rsw, 0.1f);
    const float rh  = fmaxf(reh - rsh, 0.1f);
    const float bw  = rw * (1.0f / 7.0f);
    const float bh  = rh * (1.0f / 7.0f);
    const float sw  = bw * 0.25f;
    const float sh  = bh * 0.25f;

    const float tx = __ldg(&offset[((n * 2 + 0) * POOLED + ph) * POOLED + pw]) * 0.1f;
    const float ty = __ldg(&offset[((n * 2 + 1) * POOLED + ph) * POOLED + pw]) * 0.1f;

    const float wstart = pw * bw + rsw + tx * rw;
    const float hstart = ph * bh + rsh + ty * rh;

    // ---- exact clipped footprint (x,y monotone in sample index) ----
    const float xcA = fminf(fmaxf(wstart,             0.0f), (float)(W_IN - 1));
    const float xcB = fminf(fmaxf(wstart + 3.0f * sw, 0.0f), (float)(W_IN - 1));
    const float ycA = fminf(fmaxf(hstart,             0.0f), (float)(H_IN - 1));
    const float ycB = fminf(fmaxf(hstart + 3.0f * sh, 0.0f), (float)(H_IN - 1));
    const int xlo = (int)floorf(xcA);
    const int ylo = (int)floorf(ycA);
    const int w   = min((int)ceilf(xcB) - xlo + 1, MAXT);   // 1..5, fully in-image
    const int h   = min((int)ceilf(ycB) - ylo + 1, MAXT);   // 1..5, fully in-image
    const int area   = w * h;                               // <= 25
    const int stride = area | 1;                            // odd -> conflict-free

    // ---- stage footprint with cp.async (warp-local: warp w -> channels 32w..32w+31,
    // which are exactly the channels warp w's threads consume in the dot) ----
    {
        const int yy  = lane / w;
        const int xx  = lane - yy * w;
        const int off = (ylo + yy) * W_IN + (xlo + xx);     // in-image by construction
        const float* gp = inp + (size_t)b * (C_IN * HW) + (size_t)(warp * 32) * HW + off;
        float* sp = tile + (warp * 32) * stride + lane;
        if (lane < area) {
            #pragma unroll
            for (int i = 0; i < 32; i++) {
                cp_async4(sp, gp);
                gp += HW;
                sp += stride;
            }
        }
        asm volatile("cp.async.commit_group;\n" ::: "memory");
    }

    // ---- per-warp weights: lanes 0-15 = samples, scatter-add into wacc[warp].
    // Runs while this warp's cp.asyncs are in flight. Warp-local: no block barrier.
    wacc[warp][lane] = 0.0f;
    __syncwarp();
    bool ok = false;
    if (lane < 16) {
        const int iy = lane >> 2;
        const int ix = lane & 3;
        const float x = wstart + (float)ix * sw;
        const float y = hstart + (float)iy * sh;
        ok = (x >= -0.5f) && (x <= (float)W_IN - 0.5f) &&
             (y >= -0.5f) && (y <= (float)H_IN - 0.5f);
        const float xc = fminf(fmaxf(x, 0.0f), (float)(W_IN - 1));
        const float yc = fminf(fmaxf(y, 0.0f), (float)(H_IN - 1));
        const float x0f = floorf(xc);
        const float y0f = floorf(yc);
        const float dx = xc - x0f;
        const float dy = yc - y0f;
        const int rx0 = min(max((int)x0f       - xlo, 0), w - 1);
        const int rx1 = min(max((int)ceilf(xc) - xlo, 0), w - 1);
        const int ry0 = min(max((int)y0f       - ylo, 0), h - 1);
        const int ry1 = min(max((int)ceilf(yc) - ylo, 0), h - 1);
        if (ok) {
            const float omdx = 1.0f - dx;
            const float omdy = 1.0f - dy;
            atomicAdd(&wacc[warp][ry0 * w + rx0], omdx * omdy);
            atomicAdd(&wacc[warp][ry1 * w + rx0], omdx * dy);
            atomicAdd(&wacc[warp][ry0 * w + rx1], dx * omdy);
            atomicAdd(&wacc[warp][ry1 * w + rx1], dx * dy);
        }
    }
    const float cnt = (float)__popc(__ballot_sync(0xffffffffu, ok));

    asm volatile("cp.async.wait_group 0;\n" ::: "memory");
    __syncwarp();

    // ---- thread = channel: dot(tile_row, wacc[warp]) ----
    const float* tch = tile + tid * stride;
    const float* wv  = wacc[warp];
    float dot = 0.0f;
    #pragma unroll 5
    for (int e = 0; e < area; e++)
        dot += wv[e] * tch[e];                   // wv: broadcast LDS

    out[(((size_t)n * C_IN + tid) * POOLED + ph) * POOLED + pw] =
        dot / fmaxf(cnt, 1.0f);
}

extern "C" void kernel_launch(void* const* d_in, const int* in_sizes, int n_in,
                              void* d_out, int out_size)
{
    const float* inp    = (const float*)d_in[0];   // (2, 256, 160, 160) f32
    const float* rois   = (const float*)d_in[1];   // (N, 5) f32
    const float* offset = (const float*)d_in[2];   // (N, 2, 7, 7) f32
    float* out = (float*)d_out;                    // (N, 256, 7, 7) f32

    const int N = in_sizes[1] / 5;

    dim3 grid(POOLED * POOLED, N);                 // 49 x N
    dim3 block(C_IN);
    dcnv2_pool_kernel<<<grid, block>>>(inp, rois, offset, out, N);
}

// round 8
// speedup vs baseline: 1.2973x; 1.2973x over previous
#include <cuda_runtime.h>
#include <cuda_bf16.h>

#define W_IN 160
#define H_IN 160
#define HW   (H_IN * W_IN)
#define C_IN 256
#define POOLED 7
#define MAXT 5                     // max footprint side (3*sw <= 2.16 => <=5)
#define MAXSTRIDE 25

__device__ __forceinline__ void cp_async4(float* smem_dst, const float* gmem_src) {
    unsigned s = (unsigned)__cvta_generic_to_shared(smem_dst);
    asm volatile("cp.async.ca.shared.global [%0], [%1], 4;\n" :: "r"(s), "l"(gmem_src));
}

__global__ __launch_bounds__(C_IN, 6)
void dcnv2_pool_kernel(const float* __restrict__ inp,
                       const float* __restrict__ rois,
                       const float* __restrict__ offset,
                       float* __restrict__ out,
                       int N)
{
    __shared__ float tile[C_IN * MAXSTRIDE];     // 25.6 KB

    const int bin = blockIdx.x;
    const int n   = blockIdx.y;
    const int ph  = bin / POOLED;
    const int pw  = bin % POOLED;
    const int tid = threadIdx.x;
    const int lane = tid & 31;
    const int warp = tid >> 5;

    // ---- ROI geometry (uniform across block; per-thread registers) ----
    const float* roi = rois + n * 5;
    const int   b  = (int)__ldg(&roi[0]);
    const float rsw = rintf(__ldg(&roi[1])) * 0.0625f - 0.5f;
    const float rsh = rintf(__ldg(&roi[2])) * 0.0625f - 0.5f;
    const float rew = (rintf(__ldg(&roi[3])) + 1.0f) * 0.0625f - 0.5f;
    const float reh = (rintf(__ldg(&roi[4])) + 1.0f) * 0.0625f - 0.5f;
    const float rw  = fmaxf(rew - rsw, 0.1f);
    const float rh  = fmaxf(reh - rsh, 0.1f);
    const float bw  = rw * (1.0f / 7.0f);
    const float bh  = rh * (1.0f / 7.0f);
    const float sw  = bw * 0.25f;
    const float sh  = bh * 0.25f;

    const float tx = __ldg(&offset[((n * 2 + 0) * POOLED + ph) * POOLED + pw]) * 0.1f;
    const float ty = __ldg(&offset[((n * 2 + 1) * POOLED + ph) * POOLED + pw]) * 0.1f;

    const float wstart = pw * bw + rsw + tx * rw;
    const float hstart = ph * bh + rsh + ty * rh;

    // ---- exact clipped footprint (x,y monotone in sample index) ----
    const float xcA = fminf(fmaxf(wstart,             0.0f), (float)(W_IN - 1));
    const float xcB = fminf(fmaxf(wstart + 3.0f * sw, 0.0f), (float)(W_IN - 1));
    const float ycA = fminf(fmaxf(hstart,             0.0f), (float)(H_IN - 1));
    const float ycB = fminf(fmaxf(hstart + 3.0f * sh, 0.0f), (float)(H_IN - 1));
    const int xlo = (int)floorf(xcA);
    const int ylo = (int)floorf(ycA);
    const int w   = min((int)ceilf(xcB) - xlo + 1, MAXT);   // 1..5, fully in-image
    const int h   = min((int)ceilf(ycB) - ylo + 1, MAXT);
    const int area   = w * h;                               // <= 25
    const int stride = area | 1;                            // odd -> conflict-free

    // ---- stage footprint with cp.async (warp-local: warp w covers its own
    // 32 channels, which are exactly what its threads consume in the dot) ----
    {
        const int yy  = lane / w;
        const int xx  = lane - yy * w;
        const int off = (ylo + yy) * W_IN + (xlo + xx);     // in-image by construction
        const float* gp = inp + (size_t)b * (C_IN * HW) + (size_t)(warp * 32) * HW + off;
        float* sp = tile + (warp * 32) * stride + lane;
        if (lane < area) {
            #pragma unroll
            for (int i = 0; i < 32; i++) {
                cp_async4(sp, gp);
                gp += HW;
                sp += stride;
            }
        }
        asm volatile("cp.async.commit_group;\n" ::: "memory");
    }

    // ---- separable accumulated weights (registers only; overlaps cp.async flight).
    // wacc[yy][xx] = WY[yy]*WX[xx];  WX[e] = sum_ix okX * hat(xc_ix - (xlo+e)).
    // hat(d) = max(0, 1-|d|) reproduces floor/ceil bilinear splitting exactly
    // (incl. dx==0). cnt = cntX*cntY since valid = okX & okY is separable.
    float WX[MAXT], WY[MAXT];
    #pragma unroll
    for (int e = 0; e < MAXT; e++) { WX[e] = 0.0f; WY[e] = 0.0f; }
    float cntX = 0.0f, cntY = 0.0f;
    #pragma unroll
    for (int s = 0; s < 4; s++) {
        const float x   = wstart + (float)s * sw;
        const float okx = (x >= -0.5f && x <= (float)W_IN - 0.5f) ? 1.0f : 0.0f;
        const float xc  = fminf(fmaxf(x, 0.0f), (float)(W_IN - 1));
        cntX += okx;
        #pragma unroll
        for (int e = 0; e < MAXT; e++)
            WX[e] += okx * fmaxf(1.0f - fabsf(xc - (float)(xlo + e)), 0.0f);

        const float y   = hstart + (float)s * sh;
        const float oky = (y >= -0.5f && y <= (float)H_IN - 0.5f) ? 1.0f : 0.0f;
        const float yc  = fminf(fmaxf(y, 0.0f), (float)(H_IN - 1));
        cntY += oky;
        #pragma unroll
        for (int e = 0; e < MAXT; e++)
            WY[e] += oky * fmaxf(1.0f - fabsf(yc - (float)(ylo + e)), 0.0f);
    }
    const float cnt = cntX * cntY;

    asm volatile("cp.async.wait_group 0;\n" ::: "memory");
    __syncwarp();                                // staging is warp-local

    // ---- thread = channel: separable dot over footprint ----
    const float* tch = tile + tid * stride;
    float acc = 0.0f;
    #pragma unroll
    for (int yy = 0; yy < MAXT; yy++) {
        if (yy < h) {
            float r = 0.0f;
            #pragma unroll
            for (int xx = 0; xx < MAXT; xx++) {
                if (xx < w) r += WX[xx] * tch[yy * w + xx];
            }
            acc += WY[yy] * r;
        }
    }

    out[(((size_t)n * C_IN + tid) * POOLED + ph) * POOLED + pw] =
        acc / fmaxf(cnt, 1.0f);
}

extern "C" void kernel_launch(void* const* d_in, const int* in_sizes, int n_in,
                              void* d_out, int out_size)
{
    const float* inp    = (const float*)d_in[0];   // (2, 256, 160, 160) f32
    const float* rois   = (const float*)d_in[1];   // (N, 5) f32
    const float* offset = (const float*)d_in[2];   // (N, 2, 7, 7) f32
    float* out = (float*)d_out;                    // (N, 256, 7, 7) f32

    const int N = in_sizes[1] / 5;

    dim3 grid(POOLED * POOLED, N);                 // 49 x N
    dim3 block(C_IN);
    dcnv2_pool_kernel<<<grid, block>>>(inp, rois, offset, out, N);
}